// round 3
// baseline (speedup 1.0000x reference)
#include <cuda_runtime.h>
#include <math.h>

#define NIMG 8
#define CH 3
#define HH 512
#define WW 512
#define GMIX 5
#define MF 3
#define HY 256
#define WY 256
#define NCOLS 67

// 6.3 MB scratch for downsampled y
__device__ float g_y[NIMG * CH * HY * WY];

struct Params {
    float Sinv[GMIX][6];      // symmetric 3x3: s00,s01,s02,s11,s12,s22
    float halflogdet[GMIX];
    float logpi[GMIX];
    float mu[GMIX][CH];
    float c[GMIX][MF];
    float rL[GMIX][MF];       // 1/sL
    float rR[GMIX][MF];       // 1/sR
};

__device__ __forceinline__ float softplus_f(float x) {
    if (x > 15.0f) return x;
    return log1pf(__expf(x));
}

// ---------------------------------------------------------------------------
// Kernel 1: separable 7x7 gaussian blur, reflect pad, stride 2.
// Tile: 32x8 outputs per block. Taps computed in registers.
// ---------------------------------------------------------------------------
__global__ void __launch_bounds__(256) down_kernel(const float* __restrict__ x) {
    __shared__ float xs[21][69];
    __shared__ float tmp[21][32];

    int tx = threadIdx.x & 31;
    int ty = threadIdx.x >> 5;
    int j0 = blockIdx.x * 32;
    int i0 = blockIdx.y * 8;
    int zc = blockIdx.z;  // n*CH + c
    const float* xin = x + (size_t)zc * HH * WW;

    const float inv2s2 = 1.0f / 1.62f;
    float e1 = __expf(-1.0f * inv2s2);
    float e2 = __expf(-4.0f * inv2s2);
    float e3 = __expf(-9.0f * inv2s2);
    float sinv = 1.0f / (1.0f + 2.0f * (e1 + e2 + e3));
    float gw[7] = { e3 * sinv, e2 * sinv, e1 * sinv, sinv, e1 * sinv, e2 * sinv, e3 * sinv };

    for (int idx = threadIdx.x; idx < 21 * 69; idx += 256) {
        int rr = idx / 69, cc = idx - rr * 69;
        int r = 2 * i0 - 3 + rr;
        int c = 2 * j0 - 3 + cc;
        r = (r < 0) ? -r : (r >= HH ? 2 * HH - 2 - r : r);
        c = (c < 0) ? -c : (c >= WW ? 2 * WW - 2 - c : c);
        xs[rr][cc] = xin[r * WW + c];
    }
    __syncthreads();

    for (int r = ty; r < 21; r += 8) {
        float acc = 0.f;
#pragma unroll
        for (int b = 0; b < 7; b++) acc += gw[b] * xs[r][2 * tx + b];
        tmp[r][tx] = acc;
    }
    __syncthreads();

    float acc = 0.f;
#pragma unroll
    for (int a = 0; a < 7; a++) acc += gw[a] * tmp[2 * ty + a][tx];
    g_y[((size_t)zc * HY + (i0 + ty)) * WY + (j0 + tx)] = acc;
}

// ---------------------------------------------------------------------------
// Kernel 2: fused params + upsample + GMM + fuzzy membership.
// 512 threads = 4 output rows x 128 cols. Stage 5 y-rows once, precombine
// 4 vertical-tap combos, 4-tap horizontal per pixel. Output via smem staging
// and float4 coalesced stores.
// ---------------------------------------------------------------------------
__global__ void __launch_bounds__(512) main_kernel(float* __restrict__ out,
                                                   const float* __restrict__ mu,
                                                   const float* __restrict__ L_raw,
                                                   const float* __restrict__ pi,
                                                   const float* __restrict__ mf_c,
                                                   const float* __restrict__ mf_sL,
                                                   const float* __restrict__ mf_sR) {
    __shared__ float ys[CH][5][NCOLS + 1];
    __shared__ float rc[4][CH][NCOLS + 1];
    __shared__ Params P;
    __shared__ float so[512 * GMIX * MF];

    int tx = threadIdx.x;
    int b  = blockIdx.x;
    int cg = b & 3;
    int R  = (b >> 2) & 127;
    int n  = b >> 9;
    int q0 = cg << 7;
    int p0 = R << 2;
    int r  = R << 1;   // p0/2

    // taps (uniform per thread, registers): tk = 2*g[k] pattern
    const float inv2s2 = 1.0f / 1.62f;
    float e1 = __expf(-1.0f * inv2s2);
    float e2 = __expf(-4.0f * inv2s2);
    float e3 = __expf(-9.0f * inv2s2);
    float sr = 2.0f / (1.0f + 2.0f * (e1 + e2 + e3));
    float t0 = e3 * sr, t1 = e2 * sr, t2 = e1 * sr, t3 = sr;

    // ---- per-block param computation (fp32, warp 0) ----
    if (tx < GMIX) {
        int g = tx;
        for (int i = 0; i < CH; i++) P.mu[g][i] = mu[g * CH + i];
        float L[3][3];
        for (int i = 0; i < 3; i++)
            for (int j = 0; j < 3; j++) {
                float v = L_raw[(g * 3 + i) * 3 + j];
                L[i][j] = (j < i) ? v : 0.0f;
            }
        for (int i = 0; i < 3; i++) {
            float d = softplus_f(L_raw[(g * 3 + i) * 3 + i]) + 1e-4f;  // MIN_DIAG
            d = softplus_f(d) + 1e-4f;                                  // SIG_EPS
            L[i][i] = d;
        }
        float Sg[3][3];
        for (int i = 0; i < 3; i++)
            for (int j = 0; j < 3; j++) {
                float acc = 0.0f;
                for (int k = 0; k < 3; k++) acc += L[i][k] * L[j][k];
                Sg[i][j] = acc + (i == j ? 1e-4f : 0.0f);
            }
        float det = Sg[0][0] * (Sg[1][1] * Sg[2][2] - Sg[1][2] * Sg[2][1])
                  - Sg[0][1] * (Sg[1][0] * Sg[2][2] - Sg[1][2] * Sg[2][0])
                  + Sg[0][2] * (Sg[1][0] * Sg[2][1] - Sg[1][1] * Sg[2][0]);
        P.halflogdet[g] = 0.5f * __logf(det);
        float A[3][3];
        for (int i = 0; i < 3; i++)
            for (int j = 0; j < 3; j++) A[i][j] = Sg[i][j] + (i == j ? 1e-3f : 0.0f);
        float dA = A[0][0] * (A[1][1] * A[2][2] - A[1][2] * A[2][1])
                 - A[0][1] * (A[1][0] * A[2][2] - A[1][2] * A[2][0])
                 + A[0][2] * (A[1][0] * A[2][1] - A[1][1] * A[2][0]);
        float idA = 1.0f / dA;
        P.Sinv[g][0] =  (A[1][1] * A[2][2] - A[1][2] * A[2][1]) * idA;
        P.Sinv[g][1] = -(A[0][1] * A[2][2] - A[0][2] * A[2][1]) * idA;
        P.Sinv[g][2] =  (A[0][1] * A[1][2] - A[0][2] * A[1][1]) * idA;
        P.Sinv[g][3] =  (A[0][0] * A[2][2] - A[0][2] * A[2][0]) * idA;
        P.Sinv[g][4] = -(A[0][0] * A[1][2] - A[0][2] * A[1][0]) * idA;
        P.Sinv[g][5] =  (A[0][0] * A[1][1] - A[0][1] * A[1][0]) * idA;
    } else if (tx >= 8 && tx < 8 + GMIX * MF) {
        int t = tx - 8;
        int g = t / MF, m = t - g * MF;
        P.c[g][m] = mf_c[g * MF + m];
        float sL = softplus_f(mf_sL[g * MF + m]) + 1e-12f;
        float sR = softplus_f(mf_sR[g * MF + m]) + 1e-12f;
        P.rL[g][m] = 1.0f / sL;
        P.rR[g][m] = 1.0f / sR;
    } else if (tx == 24) {
        float mx = -1e30f;
        float pv[GMIX];
        for (int g = 0; g < GMIX; g++) { pv[g] = pi[g]; mx = fmaxf(mx, pv[g]); }
        float s = 0.0f;
        for (int g = 0; g < GMIX; g++) s += __expf(pv[g] - mx);
        float lse = mx + __logf(s);
        for (int g = 0; g < GMIX; g++) P.logpi[g] = pv[g] - lse;
    }

    // ---- stage 5 y-rows x 3ch x 67 cols ----
    int n0 = (q0 >> 1) - 1;
    int r0 = r - 1;
    for (int idx = tx; idx < CH * 5 * NCOLS; idx += 512) {
        int c   = idx / (5 * NCOLS);
        int rem = idx - c * 5 * NCOLS;
        int s   = rem / NCOLS;
        int col = rem - s * NCOLS;
        int gm = r0 + s, gn = n0 + col;
        float v = 0.f;
        if (gm >= 0 && gm < HY && gn >= 0 && gn < WY)
            v = g_y[(((size_t)n * CH + c) * HY + gm) * WY + gn];
        ys[c][s][col] = v;
    }
    __syncthreads();

    // ---- precombine 4 vertical-tap combos ----
    // combo k -> output row p0+k. even k: {t1,t3,t1} from s0=k/2; odd k: {t0,t2,t2,t0}
    for (int idx = tx; idx < 4 * CH * NCOLS; idx += 512) {
        int k   = idx / (CH * NCOLS);
        int rem = idx - k * (CH * NCOLS);
        int c   = rem / NCOLS;
        int col = rem - c * NCOLS;
        int s0  = k >> 1;
        float v;
        if (k & 1)
            v = t0 * ys[c][s0][col] + t2 * ys[c][s0 + 1][col]
              + t2 * ys[c][s0 + 2][col] + t0 * ys[c][s0 + 3][col];
        else
            v = t1 * ys[c][s0][col] + t3 * ys[c][s0 + 1][col] + t1 * ys[c][s0 + 2][col];
        rc[k][c][col] = v;
    }
    __syncthreads();

    // ---- per-pixel: horizontal 4-tap + GMM + membership ----
    int row = tx >> 7;        // 0..3
    int col = tx & 127;
    int codd = col & 1;
    int cl0  = codd ? (col - 1) >> 1 : col >> 1;
    float wc0, wc1, wc2, wc3;
    if (codd) { wc0 = t0; wc1 = t2; wc2 = t2; wc3 = t0; }
    else      { wc0 = t1; wc1 = t3; wc2 = t1; wc3 = 0.f; }

    float xr[CH];
#pragma unroll
    for (int c = 0; c < CH; c++)
        xr[c] = wc0 * rc[row][c][cl0] + wc1 * rc[row][c][cl0 + 1]
              + wc2 * rc[row][c][cl0 + 2] + wc3 * rc[row][c][cl0 + 3];

    float lg[GMIX];
    float mx = -1e30f;
#pragma unroll
    for (int g = 0; g < GMIX; g++) {
        float d0 = xr[0] - P.mu[g][0];
        float d1 = xr[1] - P.mu[g][1];
        float d2 = xr[2] - P.mu[g][2];
        float quad = d0 * d0 * P.Sinv[g][0] + d1 * d1 * P.Sinv[g][3] + d2 * d2 * P.Sinv[g][5]
                   + 2.f * (d0 * d1 * P.Sinv[g][1] + d0 * d2 * P.Sinv[g][2] + d1 * d2 * P.Sinv[g][4]);
        float l = -0.5f * quad - P.halflogdet[g] + P.logpi[g];
        lg[g] = l;
        mx = fmaxf(mx, l);
    }
    float se = 0.f;
#pragma unroll
    for (int g = 0; g < GMIX; g++) { lg[g] = __expf(lg[g] - mx); se += lg[g]; }
    float sinv = __fdividef(1.f, se);

#pragma unroll
    for (int g = 0; g < GMIX; g++) {
        float xg = lg[g] * sinv;
        float z0, z1, z2;
        {
            float cgm = P.c[g][0];
            float rs = (xg < cgm) ? P.rL[g][0] : P.rR[g][0];
            float t = (xg - cgm) * rs;
            z0 = __expf(-0.5f * t * t);
        }
        {
            float cgm = P.c[g][1];
            float rs = (xg < cgm) ? P.rL[g][1] : P.rR[g][1];
            float t = (xg - cgm) * rs;
            z1 = __expf(-0.5f * t * t);
        }
        {
            float cgm = P.c[g][2];
            float rs = (xg < cgm) ? P.rL[g][2] : P.rR[g][2];
            float t = (xg - cgm) * rs;
            z2 = __expf(-0.5f * t * t);
        }
        float zin = __fdividef(1.f, z0 + z1 + z2);
        so[tx * 15 + g * 3 + 0] = z0 * zin;
        so[tx * 15 + g * 3 + 1] = z1 * zin;
        so[tx * 15 + g * 3 + 2] = z2 * zin;
    }
    __syncthreads();

    // ---- coalesced float4 stores: 4 row-segments x 480 float4 ----
    const float4* so4 = (const float4*)so;
#pragma unroll
    for (int i = 0; i < 4; i++) {
        if (tx < 480) {
            size_t base = (((size_t)n * HH + (p0 + i)) * WW + q0) * (GMIX * MF);
            float4* o4 = (float4*)(out + base);
            o4[tx] = so4[i * 480 + tx];
        }
    }
}

extern "C" void kernel_launch(void* const* d_in, const int* in_sizes, int n_in,
                              void* d_out, int out_size) {
    const float* x     = (const float*)d_in[0];
    const float* mu    = (const float*)d_in[1];
    const float* L_raw = (const float*)d_in[2];
    const float* pi    = (const float*)d_in[3];
    const float* mf_c  = (const float*)d_in[4];
    const float* mf_sL = (const float*)d_in[5];
    const float* mf_sR = (const float*)d_in[6];
    float* out = (float*)d_out;

    dim3 g1(WY / 32, HY / 8, NIMG * CH);
    down_kernel<<<g1, 256>>>(x);

    main_kernel<<<NIMG * 128 * 4, 512>>>(out, mu, L_raw, pi, mf_c, mf_sL, mf_sR);
}

// round 5
// speedup vs baseline: 1.1529x; 1.1529x over previous
#include <cuda_runtime.h>
#include <math.h>

#define NIMG 8
#define CH 3
#define HH 512
#define WW 512
#define GMIX 5
#define MF 3
#define HY 256
#define WY 256
#define NCOL 131

// 6.3 MB scratch for downsampled y
__device__ float g_y[NIMG * CH * HY * WY];

struct Params {
    float Sinv[GMIX][6];      // symmetric 3x3: s00,s01,s02,s11,s12,s22
    float halflogdet[GMIX];
    float logpi[GMIX];
    float mu[GMIX][CH];
    float c[GMIX][MF];
    float rL[GMIX][MF];       // 1/sL
    float rR[GMIX][MF];       // 1/sR
};

__device__ __forceinline__ float softplus_f(float x) {
    if (x > 15.0f) return x;
    return log1pf(__expf(x));
}

// ---------------------------------------------------------------------------
// Kernel 1: separable 7x7 gaussian blur, reflect pad, stride 2.
// Tile: 64x16 outputs per 256-thread block. No integer divides anywhere.
// ---------------------------------------------------------------------------
__global__ void __launch_bounds__(256) down_kernel(const float* __restrict__ x) {
    __shared__ float xs[37][136];   // input tile: 37 rows x 133 cols (padded)
    __shared__ float hp[37][64];    // after horizontal pass

    int tid  = threadIdx.x;
    int lane = tid & 31;
    int wid  = tid >> 5;
    int j0 = blockIdx.x * 64;
    int i0 = blockIdx.y * 16;
    int zc = blockIdx.z;  // n*CH + c
    const float* xin = x + (size_t)zc * HH * WW;

    // taps in registers (uniform)
    const float inv2s2 = 1.0f / 1.62f;
    float e1 = __expf(-1.0f * inv2s2);
    float e2 = __expf(-4.0f * inv2s2);
    float e3 = __expf(-9.0f * inv2s2);
    float sinv = 1.0f / (1.0f + 2.0f * (e1 + e2 + e3));
    float gw[7] = { e3 * sinv, e2 * sinv, e1 * sinv, sinv, e1 * sinv, e2 * sinv, e3 * sinv };

    // stage input tile: rows by warp, cols by lane (no divides)
    int rbase = 2 * i0 - 3;
    int cbase = 2 * j0 - 3;
    for (int rr = wid; rr < 37; rr += 8) {
        int r = rbase + rr;
        r = (r < 0) ? -r : (r >= HH ? 2 * HH - 2 - r : r);
        const float* xrow = xin + (size_t)r * WW;
        for (int cc = lane; cc < 133; cc += 32) {
            int c = cbase + cc;
            c = (c < 0) ? -c : (c >= WW ? 2 * WW - 2 - c : c);
            xs[rr][cc] = xrow[c];
        }
    }
    __syncthreads();

    // horizontal pass (stride-2): 37 rows x 64 cols
    for (int rr = wid; rr < 37; rr += 8) {
        for (int c = lane; c < 64; c += 32) {
            float acc = 0.f;
#pragma unroll
            for (int b = 0; b < 7; b++) acc += gw[b] * xs[rr][2 * c + b];
            hp[rr][c] = acc;
        }
    }
    __syncthreads();

    // vertical pass (stride-2): 16 rows x 64 cols, 4 rows per thread
    int c  = tid & 63;
    int r4 = tid >> 6;  // 0..3
#pragma unroll
    for (int k = 0; k < 4; k++) {
        int r = r4 + k * 4;
        float acc = 0.f;
#pragma unroll
        for (int a = 0; a < 7; a++) acc += gw[a] * hp[2 * r + a][c];
        g_y[((size_t)zc * HY + (i0 + r)) * WY + (j0 + c)] = acc;
    }
}

// ---------------------------------------------------------------------------
// Kernel 2: fused params + upsample + GMM + fuzzy membership.
// 256 threads = 256 consecutive pixels of one row. Vertical taps uniform per
// block -> precombine directly from global y into rc, 4-tap horizontal per
// pixel, smem-staged float4 coalesced output.
// ---------------------------------------------------------------------------
__global__ void __launch_bounds__(256) main_kernel(float* __restrict__ out,
                                                   const float* __restrict__ mu,
                                                   const float* __restrict__ L_raw,
                                                   const float* __restrict__ pi,
                                                   const float* __restrict__ mf_c,
                                                   const float* __restrict__ mf_sL,
                                                   const float* __restrict__ mf_sR) {
    __shared__ float rc[CH][NCOL + 1];
    __shared__ Params P;
    __shared__ float4 so4[256 * GMIX * MF / 4];
    float* so = (float*)so4;

    int tx = threadIdx.x;
    int b = blockIdx.x;
    int qb = b & 1;
    int p  = (b >> 1) & 511;
    int n  = b >> 10;
    int q0 = qb << 8;

    // taps (uniform): tk = 2*g[k]
    const float inv2s2 = 1.0f / 1.62f;
    float e1 = __expf(-1.0f * inv2s2);
    float e2 = __expf(-4.0f * inv2s2);
    float e3 = __expf(-9.0f * inv2s2);
    float sr = 2.0f / (1.0f + 2.0f * (e1 + e2 + e3));
    float t0 = e3 * sr, t1 = e2 * sr, t2 = e1 * sr, t3 = sr;

    // ---- per-block param computation (fp32) ----
    if (tx < GMIX) {
        int g = tx;
        for (int i = 0; i < CH; i++) P.mu[g][i] = mu[g * CH + i];
        float L[3][3];
        for (int i = 0; i < 3; i++)
            for (int j = 0; j < 3; j++) {
                float v = L_raw[(g * 3 + i) * 3 + j];
                L[i][j] = (j < i) ? v : 0.0f;
            }
        for (int i = 0; i < 3; i++) {
            float d = softplus_f(L_raw[(g * 3 + i) * 3 + i]) + 1e-4f;  // MIN_DIAG
            d = softplus_f(d) + 1e-4f;                                  // SIG_EPS
            L[i][i] = d;
        }
        float Sg[3][3];
        for (int i = 0; i < 3; i++)
            for (int j = 0; j < 3; j++) {
                float acc = 0.0f;
                for (int k = 0; k < 3; k++) acc += L[i][k] * L[j][k];
                Sg[i][j] = acc + (i == j ? 1e-4f : 0.0f);
            }
        float det = Sg[0][0] * (Sg[1][1] * Sg[2][2] - Sg[1][2] * Sg[2][1])
                  - Sg[0][1] * (Sg[1][0] * Sg[2][2] - Sg[1][2] * Sg[2][0])
                  + Sg[0][2] * (Sg[1][0] * Sg[2][1] - Sg[1][1] * Sg[2][0]);
        P.halflogdet[g] = 0.5f * __logf(det);
        float A[3][3];
        for (int i = 0; i < 3; i++)
            for (int j = 0; j < 3; j++) A[i][j] = Sg[i][j] + (i == j ? 1e-3f : 0.0f);
        float dA = A[0][0] * (A[1][1] * A[2][2] - A[1][2] * A[2][1])
                 - A[0][1] * (A[1][0] * A[2][2] - A[1][2] * A[2][0])
                 + A[0][2] * (A[1][0] * A[2][1] - A[1][1] * A[2][0]);
        float idA = 1.0f / dA;
        P.Sinv[g][0] =  (A[1][1] * A[2][2] - A[1][2] * A[2][1]) * idA;
        P.Sinv[g][1] = -(A[0][1] * A[2][2] - A[0][2] * A[2][1]) * idA;
        P.Sinv[g][2] =  (A[0][1] * A[1][2] - A[0][2] * A[1][1]) * idA;
        P.Sinv[g][3] =  (A[0][0] * A[2][2] - A[0][2] * A[2][0]) * idA;
        P.Sinv[g][4] = -(A[0][0] * A[1][2] - A[0][2] * A[1][0]) * idA;
        P.Sinv[g][5] =  (A[0][0] * A[1][1] - A[0][1] * A[1][0]) * idA;
    } else if (tx >= 32 && tx < 32 + GMIX * MF) {
        int t = tx - 32;
        int g = t / MF, m = t - g * MF;
        P.c[g][m] = mf_c[g * MF + m];
        float sL = softplus_f(mf_sL[g * MF + m]) + 1e-12f;
        float sR = softplus_f(mf_sR[g * MF + m]) + 1e-12f;
        P.rL[g][m] = 1.0f / sL;
        P.rR[g][m] = 1.0f / sR;
    } else if (tx == 64) {
        float mx = -1e30f;
        float pv[GMIX];
        for (int g = 0; g < GMIX; g++) { pv[g] = pi[g]; mx = fmaxf(mx, pv[g]); }
        float s = 0.0f;
        for (int g = 0; g < GMIX; g++) s += __expf(pv[g] - mx);
        float lse = mx + __logf(s);
        for (int g = 0; g < GMIX; g++) P.logpi[g] = pv[g] - lse;
    }

    // ---- precombine vertical taps directly from global y ----
    int odd = p & 1;
    int m0  = odd ? (p - 3) / 2 : p / 2 - 1;
    int n0  = (q0 >> 1) - 1;
    // tap weights by parity (uniform per block)
    float w0, w1, w2, w3;
    if (odd) { w0 = t0; w1 = t2; w2 = t2; w3 = t0; }
    else     { w0 = t1; w1 = t3; w2 = t1; w3 = 0.f; }
    int nrows = 3 + odd;
    bool rows_ok = (m0 >= 0) && (m0 + nrows - 1 < HY);

#pragma unroll
    for (int c = 0; c < CH; c++) {
        const float* yc = g_y + ((size_t)n * CH + c) * HY * WY;
        for (int col = tx; col < NCOL; col += 256) {
            int gn = n0 + col;
            float acc = 0.f;
            if ((unsigned)gn < WY) {
                const float* yp = yc + gn;
                if (rows_ok) {
                    acc = w0 * yp[(size_t)m0 * WY] + w1 * yp[(size_t)(m0 + 1) * WY]
                        + w2 * yp[(size_t)(m0 + 2) * WY];
                    if (odd) acc += w3 * yp[(size_t)(m0 + 3) * WY];
                } else {
#pragma unroll
                    for (int i = 0; i < 4; i++) {
                        int gm = m0 + i;
                        float w = (i == 0) ? w0 : (i == 1) ? w1 : (i == 2) ? w2 : w3;
                        if (i < nrows && (unsigned)gm < HY) acc += w * yp[(size_t)gm * WY];
                    }
                }
            }
            rc[c][col] = acc;
        }
    }
    __syncthreads();

    // ---- per-pixel: horizontal 4-tap + GMM + membership ----
    int codd = tx & 1;
    int cl0  = codd ? (tx - 1) >> 1 : tx >> 1;
    float wc0, wc1, wc2, wc3;
    if (codd) { wc0 = t0; wc1 = t2; wc2 = t2; wc3 = t0; }
    else      { wc0 = t1; wc1 = t3; wc2 = t1; wc3 = 0.f; }

    float xr[CH];
#pragma unroll
    for (int c = 0; c < CH; c++)
        xr[c] = wc0 * rc[c][cl0] + wc1 * rc[c][cl0 + 1]
              + wc2 * rc[c][cl0 + 2] + wc3 * rc[c][cl0 + 3];

    float lg[GMIX];
    float mx = -1e30f;
#pragma unroll
    for (int g = 0; g < GMIX; g++) {
        float d0 = xr[0] - P.mu[g][0];
        float d1 = xr[1] - P.mu[g][1];
        float d2 = xr[2] - P.mu[g][2];
        float quad = d0 * d0 * P.Sinv[g][0] + d1 * d1 * P.Sinv[g][3] + d2 * d2 * P.Sinv[g][5]
                   + 2.f * (d0 * d1 * P.Sinv[g][1] + d0 * d2 * P.Sinv[g][2] + d1 * d2 * P.Sinv[g][4]);
        float l = -0.5f * quad - P.halflogdet[g] + P.logpi[g];
        lg[g] = l;
        mx = fmaxf(mx, l);
    }
    float se = 0.f;
#pragma unroll
    for (int g = 0; g < GMIX; g++) { lg[g] = __expf(lg[g] - mx); se += lg[g]; }
    float sinv = __fdividef(1.f, se);

#pragma unroll
    for (int g = 0; g < GMIX; g++) {
        float xg = lg[g] * sinv;
        float z0, z1, z2;
        {
            float cgm = P.c[g][0];
            float rs = (xg < cgm) ? P.rL[g][0] : P.rR[g][0];
            float t = (xg - cgm) * rs;
            z0 = __expf(-0.5f * t * t);
        }
        {
            float cgm = P.c[g][1];
            float rs = (xg < cgm) ? P.rL[g][1] : P.rR[g][1];
            float t = (xg - cgm) * rs;
            z1 = __expf(-0.5f * t * t);
        }
        {
            float cgm = P.c[g][2];
            float rs = (xg < cgm) ? P.rL[g][2] : P.rR[g][2];
            float t = (xg - cgm) * rs;
            z2 = __expf(-0.5f * t * t);
        }
        float zin = __fdividef(1.f, z0 + z1 + z2);
        so[tx * 15 + g * 3 + 0] = z0 * zin;
        so[tx * 15 + g * 3 + 1] = z1 * zin;
        so[tx * 15 + g * 3 + 2] = z2 * zin;
    }
    __syncthreads();

    // ---- coalesced float4 stores: 960 float4 per block (3 full + 192 tail) ----
    size_t base = (((size_t)n * HH + p) * WW + q0) * (GMIX * MF);
    float4* o4 = (float4*)(out + base);
#pragma unroll
    for (int i = 0; i < 3; i++)
        o4[tx + i * 256] = so4[tx + i * 256];
    if (tx < 192)
        o4[tx + 768] = so4[tx + 768];
}

extern "C" void kernel_launch(void* const* d_in, const int* in_sizes, int n_in,
                              void* d_out, int out_size) {
    const float* x     = (const float*)d_in[0];
    const float* mu    = (const float*)d_in[1];
    const float* L_raw = (const float*)d_in[2];
    const float* pi    = (const float*)d_in[3];
    const float* mf_c  = (const float*)d_in[4];
    const float* mf_sL = (const float*)d_in[5];
    const float* mf_sR = (const float*)d_in[6];
    float* out = (float*)d_out;

    dim3 g1(WW / 2 / 64, HH / 2 / 16, NIMG * CH);
    down_kernel<<<g1, 256>>>(x);

    main_kernel<<<NIMG * 512 * 2, 256>>>(out, mu, L_raw, pi, mf_c, mf_sL, mf_sR);
}

// round 8
// speedup vs baseline: 1.3125x; 1.1385x over previous
#include <cuda_runtime.h>
#include <math.h>

#define NIMG 8
#define CH 3
#define HH 512
#define WW 512
#define GMIX 5
#define MF 3
#define HY 256
#define WY 256
#define NCOL 131

// 6.3 MB scratch for downsampled y
__device__ float g_y[NIMG * CH * HY * WY];

__device__ __forceinline__ float softplus_f(float x) {
    if (x > 15.0f) return x;
    return log1pf(__expf(x));
}

// ---------------------------------------------------------------------------
// Kernel 1: separable 7x7 gaussian blur, reflect pad, stride 2.
// Tile: 64x16 outputs per 256-thread block. No integer divides anywhere.
// ---------------------------------------------------------------------------
__global__ void __launch_bounds__(256) down_kernel(const float* __restrict__ x) {
    __shared__ float xs[37][136];   // input tile: 37 rows x 133 cols (padded)
    __shared__ float hp[37][64];    // after horizontal pass

    int tid  = threadIdx.x;
    int lane = tid & 31;
    int wid  = tid >> 5;
    int j0 = blockIdx.x * 64;
    int i0 = blockIdx.y * 16;
    int zc = blockIdx.z;  // n*CH + c
    const float* xin = x + (size_t)zc * HH * WW;

    const float inv2s2 = 1.0f / 1.62f;
    float e1 = __expf(-1.0f * inv2s2);
    float e2 = __expf(-4.0f * inv2s2);
    float e3 = __expf(-9.0f * inv2s2);
    float sinv = 1.0f / (1.0f + 2.0f * (e1 + e2 + e3));
    float gw[7] = { e3 * sinv, e2 * sinv, e1 * sinv, sinv, e1 * sinv, e2 * sinv, e3 * sinv };

    int rbase = 2 * i0 - 3;
    int cbase = 2 * j0 - 3;
    for (int rr = wid; rr < 37; rr += 8) {
        int r = rbase + rr;
        r = (r < 0) ? -r : (r >= HH ? 2 * HH - 2 - r : r);
        const float* xrow = xin + (size_t)r * WW;
        for (int cc = lane; cc < 133; cc += 32) {
            int c = cbase + cc;
            c = (c < 0) ? -c : (c >= WW ? 2 * WW - 2 - c : c);
            xs[rr][cc] = xrow[c];
        }
    }
    __syncthreads();

    for (int rr = wid; rr < 37; rr += 8) {
        for (int c = lane; c < 64; c += 32) {
            float acc = 0.f;
#pragma unroll
            for (int b = 0; b < 7; b++) acc += gw[b] * xs[rr][2 * c + b];
            hp[rr][c] = acc;
        }
    }
    __syncthreads();

    int c  = tid & 63;
    int r4 = tid >> 6;  // 0..3
#pragma unroll
    for (int k = 0; k < 4; k++) {
        int r = r4 + k * 4;
        float acc = 0.f;
#pragma unroll
        for (int a = 0; a < 7; a++) acc += gw[a] * hp[2 * r + a][c];
        g_y[((size_t)zc * HY + (i0 + r)) * WY + (j0 + c)] = acc;
    }
}

// ---------------------------------------------------------------------------
// Kernel 2: fused params + upsample + GMM + fuzzy membership.
// Base-2 exponentials throughout; float4-packed params and rc.
//   GMM logit (base2):  l = k + b.x - x^T S^ x  -> 9 FMA via packed coefs.
//   Membership: u=(xg-c)*rs', exponent=-u^2 (already base2); ratio form
//   needs only 2 EX2 + 1 RCP per g.
// ---------------------------------------------------------------------------
__global__ void __launch_bounds__(256) main_kernel(float* __restrict__ out,
                                                   const float* __restrict__ mu,
                                                   const float* __restrict__ L_raw,
                                                   const float* __restrict__ pi,
                                                   const float* __restrict__ mf_c,
                                                   const float* __restrict__ mf_sL,
                                                   const float* __restrict__ mf_sR) {
    __shared__ float4 rcv[NCOL + 1];        // (ch0,ch1,ch2,pad) per column
    __shared__ float4 Pg[GMIX * 3];         // GMM coefs: [a00,a11,a22,a01][a02,a12,b0,b1][b2,k,-,-]
    __shared__ float4 Pm[GMIX * MF];        // membership: [c, rL2, rR2, -]
    __shared__ float4 so4[256 * GMIX * MF / 4];
    float* so = (float*)so4;

    const float LOG2E = 1.4426950408889634f;
    const float SQH   = 0.8493218002880191f;  // sqrt(0.5*log2e)

    int tx = threadIdx.x;
    int b = blockIdx.x;
    int qb = b & 1;
    int p  = (b >> 1) & 511;
    int n  = b >> 10;
    int q0 = qb << 8;

    // taps (uniform): tk = 2*g[k]
    const float inv2s2 = 1.0f / 1.62f;
    float e1 = __expf(-1.0f * inv2s2);
    float e2 = __expf(-4.0f * inv2s2);
    float e3 = __expf(-9.0f * inv2s2);
    float sr = 2.0f / (1.0f + 2.0f * (e1 + e2 + e3));
    float t0 = e3 * sr, t1 = e2 * sr, t2 = e1 * sr, t3 = sr;

    // ---- per-block param computation (fp32) ----
    if (tx < GMIX) {
        int g = tx;
        float m0v = mu[g * CH + 0], m1v = mu[g * CH + 1], m2v = mu[g * CH + 2];
        float L[3][3];
        for (int i = 0; i < 3; i++)
            for (int j = 0; j < 3; j++) {
                float v = L_raw[(g * 3 + i) * 3 + j];
                L[i][j] = (j < i) ? v : 0.0f;
            }
        for (int i = 0; i < 3; i++) {
            float d = softplus_f(L_raw[(g * 3 + i) * 3 + i]) + 1e-4f;  // MIN_DIAG
            d = softplus_f(d) + 1e-4f;                                  // SIG_EPS
            L[i][i] = d;
        }
        float Sg[3][3];
        for (int i = 0; i < 3; i++)
            for (int j = 0; j < 3; j++) {
                float acc = 0.0f;
                for (int k = 0; k < 3; k++) acc += L[i][k] * L[j][k];
                Sg[i][j] = acc + (i == j ? 1e-4f : 0.0f);
            }
        float det = Sg[0][0] * (Sg[1][1] * Sg[2][2] - Sg[1][2] * Sg[2][1])
                  - Sg[0][1] * (Sg[1][0] * Sg[2][2] - Sg[1][2] * Sg[2][0])
                  + Sg[0][2] * (Sg[1][0] * Sg[2][1] - Sg[1][1] * Sg[2][0]);
        float A[3][3];
        for (int i = 0; i < 3; i++)
            for (int j = 0; j < 3; j++) A[i][j] = Sg[i][j] + (i == j ? 1e-3f : 0.0f);
        float dA = A[0][0] * (A[1][1] * A[2][2] - A[1][2] * A[2][1])
                 - A[0][1] * (A[1][0] * A[2][2] - A[1][2] * A[2][0])
                 + A[0][2] * (A[1][0] * A[2][1] - A[1][1] * A[2][0]);
        float idA = 1.0f / dA;
        float s00 =  (A[1][1] * A[2][2] - A[1][2] * A[2][1]) * idA;
        float s01 = -(A[0][1] * A[2][2] - A[0][2] * A[2][1]) * idA;
        float s02 =  (A[0][1] * A[1][2] - A[0][2] * A[1][1]) * idA;
        float s11 =  (A[0][0] * A[2][2] - A[0][2] * A[2][0]) * idA;
        float s12 = -(A[0][0] * A[1][2] - A[0][2] * A[1][0]) * idA;
        float s22 =  (A[0][0] * A[1][1] - A[0][1] * A[1][0]) * idA;
        // base-2 scaled: Shat = 0.5*log2e * Sinv
        float h = 0.5f * LOG2E;
        float q00 = h * s00, q01 = h * s01, q02 = h * s02;
        float q11 = h * s11, q12 = h * s12, q22 = h * s22;
        // b = 2 Shat mu
        float b0 = 2.f * (q00 * m0v + q01 * m1v + q02 * m2v);
        float b1 = 2.f * (q01 * m0v + q11 * m1v + q12 * m2v);
        float b2 = 2.f * (q02 * m0v + q12 * m1v + q22 * m2v);
        // logpi in base-2
        float mx = -1e30f;
        float pv[GMIX];
        for (int gg = 0; gg < GMIX; gg++) { pv[gg] = pi[gg]; mx = fmaxf(mx, pv[gg]); }
        float s = 0.0f;
        for (int gg = 0; gg < GMIX; gg++) s += __expf(pv[gg] - mx);
        float lp2 = LOG2E * (pv[g] - mx - __logf(s));
        // k = lp2 - 0.5*log2(det) - mu^T Shat mu  (= lp2 - 0.5log2det - 0.5 b.mu)
        float kcst = lp2 - 0.5f * __log2f(det) - 0.5f * (b0 * m0v + b1 * m1v + b2 * m2v);
        Pg[g * 3 + 0] = make_float4(-q00, -q11, -q22, -2.f * q01);
        Pg[g * 3 + 1] = make_float4(-2.f * q02, -2.f * q12, b0, b1);
        Pg[g * 3 + 2] = make_float4(b2, kcst, 0.f, 0.f);
    } else if (tx >= 32 && tx < 32 + GMIX * MF) {
        int t = tx - 32;
        int g = t / MF, m = t - g * MF;
        float cv = mf_c[g * MF + m];
        float sL = softplus_f(mf_sL[g * MF + m]) + 1e-12f;
        float sR = softplus_f(mf_sR[g * MF + m]) + 1e-12f;
        Pm[g * MF + m] = make_float4(cv, SQH / sL, SQH / sR, 0.f);
    }

    // ---- precombine vertical taps directly from global y (float4 per col) ----
    int odd = p & 1;
    int m0  = odd ? (p - 3) / 2 : p / 2 - 1;
    int n0  = (q0 >> 1) - 1;
    float w0, w1, w2, w3;
    if (odd) { w0 = t0; w1 = t2; w2 = t2; w3 = t0; }
    else     { w0 = t1; w1 = t3; w2 = t1; w3 = 0.f; }
    int nrows = 3 + odd;
    bool rows_ok = (m0 >= 0) && (m0 + nrows - 1 < HY);

    if (tx < NCOL) {
        int gn = n0 + tx;
        float a0 = 0.f, a1 = 0.f, a2 = 0.f;
        if ((unsigned)gn < WY) {
            const float* ybase = g_y + ((size_t)n * CH) * HY * WY + gn;
            if (rows_ok) {
#pragma unroll
                for (int c = 0; c < CH; c++) {
                    const float* yp = ybase + (size_t)c * HY * WY;
                    float acc = w0 * yp[(size_t)m0 * WY] + w1 * yp[(size_t)(m0 + 1) * WY]
                              + w2 * yp[(size_t)(m0 + 2) * WY];
                    if (odd) acc += w3 * yp[(size_t)(m0 + 3) * WY];
                    if (c == 0) a0 = acc; else if (c == 1) a1 = acc; else a2 = acc;
                }
            } else {
#pragma unroll
                for (int c = 0; c < CH; c++) {
                    const float* yp = ybase + (size_t)c * HY * WY;
                    float acc = 0.f;
#pragma unroll
                    for (int i = 0; i < 4; i++) {
                        int gm = m0 + i;
                        float w = (i == 0) ? w0 : (i == 1) ? w1 : (i == 2) ? w2 : w3;
                        if (i < nrows && (unsigned)gm < HY) acc += w * yp[(size_t)gm * WY];
                    }
                    if (c == 0) a0 = acc; else if (c == 1) a1 = acc; else a2 = acc;
                }
            }
        }
        rcv[tx] = make_float4(a0, a1, a2, 0.f);
    }
    __syncthreads();

    // ---- per-pixel: horizontal 4-tap + GMM + membership ----
    int codd = tx & 1;
    int cl0  = codd ? (tx - 1) >> 1 : tx >> 1;
    float wc0, wc1, wc2, wc3;
    if (codd) { wc0 = t0; wc1 = t2; wc2 = t2; wc3 = t0; }
    else      { wc0 = t1; wc1 = t3; wc2 = t1; wc3 = 0.f; }

    float4 v0 = rcv[cl0], v1 = rcv[cl0 + 1], v2 = rcv[cl0 + 2], v3 = rcv[cl0 + 3];
    float x0 = wc0 * v0.x + wc1 * v1.x + wc2 * v2.x + wc3 * v3.x;
    float x1 = wc0 * v0.y + wc1 * v1.y + wc2 * v2.y + wc3 * v3.y;
    float x2 = wc0 * v0.z + wc1 * v1.z + wc2 * v2.z + wc3 * v3.z;

    // shared cross products
    float p00 = x0 * x0, p11 = x1 * x1, p22 = x2 * x2;
    float p01 = x0 * x1, p02 = x0 * x2, p12 = x1 * x2;

    float lg[GMIX];
    float mx = -1e30f;
#pragma unroll
    for (int g = 0; g < GMIX; g++) {
        float4 A = Pg[g * 3 + 0];
        float4 B = Pg[g * 3 + 1];
        float4 C = Pg[g * 3 + 2];
        float l = C.y;
        l += A.x * p00; l += A.y * p11; l += A.z * p22;
        l += A.w * p01; l += B.x * p02; l += B.y * p12;
        l += B.z * x0;  l += B.w * x1;  l += C.x * x2;
        lg[g] = l;
        mx = fmaxf(mx, l);
    }
    float se = 0.f;
#pragma unroll
    for (int g = 0; g < GMIX; g++) { lg[g] = exp2f(lg[g] - mx); se += lg[g]; }
    float sinv = __fdividef(1.f, se);

#pragma unroll
    for (int g = 0; g < GMIX; g++) {
        float xg = lg[g] * sinv;
        float4 M0 = Pm[g * MF + 0];
        float4 M1 = Pm[g * MF + 1];
        float4 M2 = Pm[g * MF + 2];
        float u0 = (xg - M0.x) * ((xg < M0.x) ? M0.y : M0.z);
        float u1 = (xg - M1.x) * ((xg < M1.x) ? M1.y : M1.z);
        float u2 = (xg - M2.x) * ((xg < M2.x) ? M2.y : M2.z);
        float z0 = u0 * u0, z1 = u1 * u1, z2 = u2 * u2;   // exponent = -z (base 2)
        float r01 = exp2f(z1 - z0);
        float r21 = exp2f(z1 - z2);
        float mb1 = __fdividef(1.f, r01 + 1.f + r21);
        so[tx * 15 + g * 3 + 0] = r01 * mb1;
        so[tx * 15 + g * 3 + 1] = mb1;
        so[tx * 15 + g * 3 + 2] = r21 * mb1;
    }
    __syncthreads();

    // ---- coalesced float4 stores: 960 float4 per block ----
    size_t base = (((size_t)n * HH + p) * WW + q0) * (GMIX * MF);
    float4* o4 = (float4*)(out + base);
#pragma unroll
    for (int i = 0; i < 3; i++)
        o4[tx + i * 256] = so4[tx + i * 256];
    if (tx < 192)
        o4[tx + 768] = so4[tx + 768];
}

extern "C" void kernel_launch(void* const* d_in, const int* in_sizes, int n_in,
                              void* d_out, int out_size) {
    const float* x     = (const float*)d_in[0];
    const float* mu    = (const float*)d_in[1];
    const float* L_raw = (const float*)d_in[2];
    const float* pi    = (const float*)d_in[3];
    const float* mf_c  = (const float*)d_in[4];
    const float* mf_sL = (const float*)d_in[5];
    const float* mf_sR = (const float*)d_in[6];
    float* out = (float*)d_out;

    dim3 g1(WW / 2 / 64, HH / 2 / 16, NIMG * CH);
    down_kernel<<<g1, 256>>>(x);

    main_kernel<<<NIMG * 512 * 2, 256>>>(out, mu, L_raw, pi, mf_c, mf_sL, mf_sR);
}